// round 16
// baseline (speedup 1.0000x reference)
#include <cuda_runtime.h>
#include <cuda_fp16.h>
#include <cstdint>
#include <math.h>

// Problem constants (LinearAttention_22943715295778)
#define PB 4
#define PN 8192
#define PM 2048
#define PC 512
#define PL 256
#define PH 8
#define DL 32   // L/H
#define DC 64   // C/H
#define EPS 1e-6f

#define KV_SZ (PB*PH*DC*DL)                       // 65536
#define NACC (KV_SZ + PB*PH*DL)                   // 66560
#define S_NSPLIT 9

// -------- device-global scratch (allocation-free requirement) --------
__device__ __half g_kt[PB * PH * DL * PN];        // 16 MB : k^T [b*256+dg][n], fp16, post-elu
__device__ __half g_xt[PB * PC * PN];             // 32 MB : X^T [b*512+c'][n], fp16
__device__ __half g_qp[PB * PM * PL];             //  4 MB : q [row][256], fp16, post-elu
__device__ __half g_Sp[S_NSPLIT * PB * 256 * 512];//  9 MB : fp16 split partials of S^T
__device__ float  g_acc[NACC];                    // kv (65536) + ksum (1024)
__device__ __half g_wth[1024 * PC];               // rows: [WkT 256][WvT 512][WqT 256], fp16
__device__ float  g_bias[1024];                   // [bk | bv | bq]

// ===================== helpers =====================
__device__ __forceinline__ uint32_t smem_u32(const void* p) {
    uint32_t a;
    asm("{ .reg .u64 t; cvta.to.shared.u64 t, %1; cvt.u32.u64 %0, t; }"
        : "=r"(a) : "l"(p));
    return a;
}
// pack two fp32 -> one fp16x2 register (F2FP.PACK); lo in low half
__device__ __forceinline__ uint32_t pack_h2(float lo, float hi) {
    uint32_t r;
    asm("cvt.rn.f16x2.f32 %0, %1, %2;" : "=r"(r) : "f"(hi), "f"(lo));
    return r;
}

// ===================== prep: weight transposes + bias + zero =====================
__global__ __launch_bounds__(256) void prep_kernel(
    const float* __restrict__ Wk, const float* __restrict__ Wv,
    const float* __restrict__ Wq,
    const float* __restrict__ bk, const float* __restrict__ bv,
    const float* __restrict__ bq)
{
    __shared__ float tile[32][33];
    const int n0 = blockIdx.x * 32, k0 = blockIdx.y * 32;
    const float *W, *bsrc; int N, ns;
    if (n0 < 256)      { W = Wk; bsrc = bk; N = PL; ns = n0; }
    else if (n0 < 768) { W = Wv; bsrc = bv; N = PC; ns = n0 - 256; }
    else               { W = Wq; bsrc = bq; N = PL; ns = n0 - 768; }
    const int tx = threadIdx.x, ty = threadIdx.y;
    for (int i = ty; i < 32; i += 8)
        tile[i][tx] = W[(size_t)(k0 + i) * N + ns + tx];
    __syncthreads();
    for (int i = ty; i < 32; i += 8)
        g_wth[(size_t)(n0 + i) * PC + k0 + tx] = __float2half_rn(tile[tx][i]);
    if (blockIdx.y == 0 && ty == 0)
        g_bias[n0 + tx] = bsrc[ns + tx];
    if (blockIdx.y == 1) {
        int t = ty * 32 + tx;
#pragma unroll
        for (int i = 0; i < 9; i++) {
            int j = blockIdx.x * 256 + t + i * 8192;
            if (j < NACC) g_acc[j] = 0.0f;
        }
    }
}

// ===================== fp16 mma mainloop, fp32 A operand =====================
#define TMm 128
#define TNn 128
#define BKh 64
#define ASW 64                        // fp32 words per A row (XOR swizzled)
#define BSW 40                        // uint32 words per fp16 row (64 fp16 + pad)
#define ATILEW (128 * ASW)
#define BTILEW (128 * BSW)
#define NCHh (PC / BKh)               // 8
#define SMEM_GEMM ((2 * ATILEW + 2 * BTILEW) * 4)   // 106496 bytes

__device__ __forceinline__ void mma_tile_loop_f32a(
    const float* __restrict__ Ag0,
    const __half* __restrict__ Bg0,
    uint32_t* sm, int t, float acc[2][8][4],
    int cx0, __half* __restrict__ xt_dst, int xt_n0)
{
    uint32_t* As = sm;
    uint32_t* Bs = sm + 2 * ATILEW;
    const int wid = t >> 5, lane = t & 31;
    const int lr = lane >> 2, lc = lane & 3;
    const int wm = (wid & 3) * 32, wn = (wid >> 2) * 64;

    auto stage = [&](int c, int buf) {
        const float*  Ag = Ag0 + c * BKh;
        const __half* Bg = Bg0 + c * BKh;
        uint32_t* Ad = As + buf * ATILEW;
        uint32_t* Bd = Bs + buf * BTILEW;
#pragma unroll
        for (int i = 0; i < 8; i++) {
            int idx = i * 256 + t;
            int r = idx >> 4, s = idx & 15;
            int ss = s ^ ((r & 1) << 2);
            asm volatile("cp.async.cg.shared.global [%0], [%1], 16;"
                :: "r"(smem_u32(Ad + r * ASW + ss * 4)),
                   "l"(Ag + (size_t)r * PC + s * 4));
        }
#pragma unroll
        for (int i = 0; i < 4; i++) {
            int idx = i * 256 + t;
            int r = idx >> 3, s = idx & 7;
            asm volatile("cp.async.cg.shared.global [%0], [%1], 16;"
                :: "r"(smem_u32(Bd + r * BSW + s * 4)),
                   "l"(Bg + (size_t)r * PC + s * 8));
        }
        asm volatile("cp.async.commit_group;" ::: "memory");
    };

    auto compute = [&](int buf) {
        const uint32_t* Ab = As + buf * ATILEW;
        const uint32_t* Bb = Bs + buf * BTILEW;
#pragma unroll
        for (int j = 0; j < 4; j++) {
            uint32_t af[2][4], bf[8][2];
            const int aoff = 16 * (j ^ (lr & 1)) + 4 * lc;
#pragma unroll
            for (int mi = 0; mi < 2; mi++) {
                const int r0 = wm + mi * 16 + lr;
                float4 f0 = *(const float4*)(Ab + r0 * ASW + aoff);
                float4 f1 = *(const float4*)(Ab + (r0 + 8) * ASW + aoff);
                af[mi][0] = pack_h2(f0.x, f0.y);
                af[mi][2] = pack_h2(f0.z, f0.w);
                af[mi][1] = pack_h2(f1.x, f1.y);
                af[mi][3] = pack_h2(f1.z, f1.w);
            }
            const int ko = 8 * j + 2 * lc;
#pragma unroll
            for (int ni = 0; ni < 8; ni++) {
                uint2 b = *(const uint2*)&Bb[(wn + ni * 8 + lr) * BSW + ko];
                bf[ni][0] = b.x; bf[ni][1] = b.y;
            }
#pragma unroll
            for (int mi = 0; mi < 2; mi++)
#pragma unroll
                for (int ni = 0; ni < 8; ni++)
                    asm volatile(
                        "mma.sync.aligned.m16n8k16.row.col.f32.f16.f16.f32 "
                        "{%0,%1,%2,%3}, {%4,%5,%6,%7}, {%8,%9}, {%0,%1,%2,%3};"
                        : "+f"(acc[mi][ni][0]), "+f"(acc[mi][ni][1]),
                          "+f"(acc[mi][ni][2]), "+f"(acc[mi][ni][3])
                        : "r"(af[mi][0]), "r"(af[mi][1]),
                          "r"(af[mi][2]), "r"(af[mi][3]),
                          "r"(bf[ni][0]), "r"(bf[ni][1]));
        }
    };

    // Fused X^T write (same as round 15; reads staged fp32 A tile).
    auto xt_write = [&](int c, int buf) {
        const uint32_t* Ab = As + buf * ATILEW;
        const int cw = (wid & 1) * 32 + lane;
        const int rb = (wid >> 1) * 32;
        __half* dst = xt_dst + (size_t)(c * BKh + cw) * PN + xt_n0 + rb;
        const int cbase = ((cw >> 2) << 2) + (cw & 3);
#pragma unroll
        for (int g = 0; g < 4; g++) {
            uint32_t h2[4];
#pragma unroll
            for (int p = 0; p < 4; p++) {
                int r0 = rb + g * 8 + 2 * p;
                float f0 = __uint_as_float(
                    Ab[r0 * ASW + (cbase ^ (((r0 & 1) << 4)))]);
                float f1 = __uint_as_float(
                    Ab[(r0 + 1) * ASW + (cbase ^ ((((r0 + 1) & 1) << 4)))]);
                h2[p] = pack_h2(f0, f1);
            }
            uint4 val = {h2[0], h2[1], h2[2], h2[3]};
            *(uint4*)(dst + g * 8) = val;
        }
    };

    stage(0, 0);
    for (int c = 0; c < NCHh; c++) {
        if (c + 1 < NCHh) {
            stage(c + 1, (c + 1) & 1);
            asm volatile("cp.async.wait_group 1;" ::: "memory");
        } else {
            asm volatile("cp.async.wait_group 0;" ::: "memory");
        }
        __syncthreads();
        compute(c & 1);
        if (xt_dst && c >= cx0 && c < cx0 + 4)
            xt_write(c, c & 1);
        __syncthreads();
    }
}

// ===================== k|q projection (+fused X^T) kernel =====================
#define TSTR 136   // fp16 stride of k-transpose buffer rows

__global__ __launch_bounds__(256, 2) void kvq_gemm_kernel(
    const float* __restrict__ X, const float* __restrict__ Q)
{
    extern __shared__ uint32_t smw[];
    const int id = blockIdx.x;
    const int t = threadIdx.x;

    float acc[2][8][4];
#pragma unroll
    for (int mi = 0; mi < 2; mi++)
#pragma unroll
        for (int ni = 0; ni < 8; ni++)
#pragma unroll
            for (int j = 0; j < 4; j++) acc[mi][ni][j] = 0.0f;

    if (id < 512) {
        // ---- k projection GEMM + fused X^T write ----
        const int panel = id >> 1, sub = id & 1;
        const int row0 = panel * TMm;
        const int col0 = sub * TNn;   // 0 or 128
        const int b = row0 >> 13, n0 = row0 & 8191;

        mma_tile_loop_f32a(X + (size_t)row0 * PC, g_wth + (size_t)col0 * PC,
                           smw, t, acc,
                           sub * 4, g_xt + (size_t)b * PC * PN, n0);

        const int wid = t >> 5, lane = t & 31, lr = lane >> 2, lc = lane & 3;
        const int wm = (wid & 3) * 32, wn = (wid >> 2) * 64;

        __half* st = (__half*)smw;   // [128 cols][TSTR]
#pragma unroll
        for (int mi = 0; mi < 2; mi++)
#pragma unroll
            for (int ni = 0; ni < 8; ni++) {
                int r  = wm + mi * 16 + lr;
                int cc = wn + ni * 8 + 2 * lc;
                float b0 = g_bias[col0 + cc], b1 = g_bias[col0 + cc + 1];
                float x0 = acc[mi][ni][0] + b0;
                float x1 = acc[mi][ni][1] + b1;
                float x2 = acc[mi][ni][2] + b0;
                float x3 = acc[mi][ni][3] + b1;
                x0 = x0 > 0.0f ? x0 + 1.0f : expf(x0);
                x1 = x1 > 0.0f ? x1 + 1.0f : expf(x1);
                x2 = x2 > 0.0f ? x2 + 1.0f : expf(x2);
                x3 = x3 > 0.0f ? x3 + 1.0f : expf(x3);
                st[cc * TSTR + r]           = __float2half_rn(x0);
                st[(cc + 1) * TSTR + r]     = __float2half_rn(x1);
                st[cc * TSTR + r + 8]       = __float2half_rn(x2);
                st[(cc + 1) * TSTR + r + 8] = __float2half_rn(x3);
            }
        __syncthreads();

#pragma unroll
        for (int i = 0; i < 8; i++) {
            int flat = t + i * 256;
            int col = flat >> 4, seg = flat & 15;
            uint4 val = *(const uint4*)&st[col * TSTR + seg * 8];
            int dg = col0 + col;
            *(uint4*)&g_kt[(size_t)(b * 256 + dg) * PN + n0 + seg * 8] = val;
        }
        return;
    }

    // ---- q projection GEMM ----
    const int j = id - 512;
    const int col0 = 768 + (j & 1) * TNn;
    const int row0 = (j >> 1) * TMm;

    mma_tile_loop_f32a(Q + (size_t)row0 * PC, g_wth + (size_t)col0 * PC,
                       smw, t, acc, 0, nullptr, 0);

    const int wid = t >> 5, lane = t & 31, lr = lane >> 2, lc = lane & 3;
    const int wm = (wid & 3) * 32, wn = (wid >> 2) * 64;
#pragma unroll
    for (int mi = 0; mi < 2; mi++)
#pragma unroll
        for (int ni = 0; ni < 8; ni++) {
            int r  = row0 + wm + mi * 16 + lr;
            int cb = wn + ni * 8 + 2 * lc;
            int cc = (col0 - 768) + cb;
            float b0 = g_bias[col0 + cb];
            float b1 = g_bias[col0 + cb + 1];
            float x0 = acc[mi][ni][0] + b0;
            float x1 = acc[mi][ni][1] + b1;
            float x2 = acc[mi][ni][2] + b0;
            float x3 = acc[mi][ni][3] + b1;
            x0 = x0 > 0.0f ? x0 + 1.0f : expf(x0);
            x1 = x1 > 0.0f ? x1 + 1.0f : expf(x1);
            x2 = x2 > 0.0f ? x2 + 1.0f : expf(x2);
            x3 = x3 > 0.0f ? x3 + 1.0f : expf(x3);
            *(uint32_t*)&g_qp[(size_t)r * PL + cc]       = pack_h2(x0, x1);
            *(uint32_t*)&g_qp[(size_t)(r + 8) * PL + cc] = pack_h2(x2, x3);
        }
}

// ===================== S kernel: S^T[d][c'] = sum_n kt[d][n] * xt[c'][n] =====================
// grid (32, 9): uneven n-splits (chunks [y*128/9, (y+1)*128/9)) -> 288 CTAs
// fill the 296 resident slots nearly perfectly.
#define SMEM_S (4 * BTILEW * 4)         // 81920 bytes

__global__ __launch_bounds__(256, 2) void s_gemm_kernel()
{
    extern __shared__ uint32_t smw[];
    uint32_t* As = smw;                 // kt tiles [2][128][BSW]
    uint32_t* Bs = smw + 2 * BTILEW;    // xt tiles [2][128][BSW]

    const int bx = blockIdx.x;
    const int cblk = bx & 3;
    const int dblk = (bx >> 2) & 1;
    const int b    = bx >> 3;
    const int y    = blockIdx.y;
    const int cst  = (y * 128) / S_NSPLIT;         // first chunk
    const int nch  = ((y + 1) * 128) / S_NSPLIT - cst;
    const int n0   = cst * BKh;
    const int t = threadIdx.x;
    const int wid = t >> 5, lane = t & 31, lr = lane >> 2, lc = lane & 3;
    const int wm = (wid & 3) * 32, wn = (wid >> 2) * 64;

    const __half* Ag0 = g_kt + (size_t)(b * 256 + dblk * 128) * PN + n0;
    const __half* Bg0 = g_xt + (size_t)(b * PC  + cblk * 128) * PN + n0;

    auto stage = [&](int c, int buf) {
        const __half* Ag = Ag0 + c * BKh;
        const __half* Bg = Bg0 + c * BKh;
        uint32_t* Ad = As + buf * BTILEW;
        uint32_t* Bd = Bs + buf * BTILEW;
#pragma unroll
        for (int i = 0; i < 4; i++) {
            int idx = i * 256 + t;
            int r = idx >> 3, seg = idx & 7;
            asm volatile("cp.async.cg.shared.global [%0], [%1], 16;"
                :: "r"(smem_u32(Ad + r * BSW + seg * 4)),
                   "l"(Ag + (size_t)r * PN + seg * 8));
            asm volatile("cp.async.cg.shared.global [%0], [%1], 16;"
                :: "r"(smem_u32(Bd + r * BSW + seg * 4)),
                   "l"(Bg + (size_t)r * PN + seg * 8));
        }
        asm volatile("cp.async.commit_group;" ::: "memory");
    };

    float acc[2][8][4];
#pragma unroll
    for (int mi = 0; mi < 2; mi++)
#pragma unroll
        for (int ni = 0; ni < 8; ni++)
#pragma unroll
            for (int j = 0; j < 4; j++) acc[mi][ni][j] = 0.0f;
    float ksacc = 0.0f;

    auto compute = [&](int buf) {
        const uint32_t* Ab = As + buf * BTILEW;
        const uint32_t* Bb = Bs + buf * BTILEW;
#pragma unroll
        for (int j = 0; j < 4; j++) {
            const int ko = 8 * j + 2 * lc;
            uint32_t af[2][4], bf[8][2];
#pragma unroll
            for (int mi = 0; mi < 2; mi++) {
                uint2 lo = *(const uint2*)&Ab[(wm + mi * 16 + lr) * BSW + ko];
                uint2 hi = *(const uint2*)&Ab[(wm + mi * 16 + lr + 8) * BSW + ko];
                af[mi][0] = lo.x; af[mi][1] = hi.x;
                af[mi][2] = lo.y; af[mi][3] = hi.y;
            }
#pragma unroll
            for (int ni = 0; ni < 8; ni++) {
                uint2 bb = *(const uint2*)&Bb[(wn + ni * 8 + lr) * BSW + ko];
                bf[ni][0] = bb.x; bf[ni][1] = bb.y;
            }
#pragma unroll
            for (int mi = 0; mi < 2; mi++)
#pragma unroll
                for (int ni = 0; ni < 8; ni++)
                    asm volatile(
                        "mma.sync.aligned.m16n8k16.row.col.f32.f16.f16.f32 "
                        "{%0,%1,%2,%3}, {%4,%5,%6,%7}, {%8,%9}, {%0,%1,%2,%3};"
                        : "+f"(acc[mi][ni][0]), "+f"(acc[mi][ni][1]),
                          "+f"(acc[mi][ni][2]), "+f"(acc[mi][ni][3])
                        : "r"(af[mi][0]), "r"(af[mi][1]),
                          "r"(af[mi][2]), "r"(af[mi][3]),
                          "r"(bf[ni][0]), "r"(bf[ni][1]));
        }
        if (cblk == 0) {   // ksum partial: thread t sums half of row t>>1
            const uint32_t* kp = Ab + (t >> 1) * BSW + (t & 1) * 16;
#pragma unroll
            for (int i = 0; i < 16; i++) {
                float2 f = __half22float2(*(const __half2*)&kp[i]);
                ksacc += f.x + f.y;
            }
        }
    };

    stage(0, 0);
    for (int c = 0; c < nch; c++) {
        if (c + 1 < nch) {
            stage(c + 1, (c + 1) & 1);
            asm volatile("cp.async.wait_group 1;" ::: "memory");
        } else {
            asm volatile("cp.async.wait_group 0;" ::: "memory");
        }
        __syncthreads();
        compute(c & 1);
        __syncthreads();
    }

    // non-atomic fp16 partial store
    __half* dst = g_Sp + ((size_t)(y * PB + b) * 256 + dblk * 128) * 512
                  + cblk * 128;
#pragma unroll
    for (int mi = 0; mi < 2; mi++)
#pragma unroll
        for (int ni = 0; ni < 8; ni++) {
            int row = wm + mi * 16 + lr;
            int col = wn + ni * 8 + 2 * lc;
            *(uint32_t*)&dst[(size_t)row * 512 + col] =
                pack_h2(acc[mi][ni][0], acc[mi][ni][1]);
            *(uint32_t*)&dst[(size_t)(row + 8) * 512 + col] =
                pack_h2(acc[mi][ni][2], acc[mi][ni][3]);
        }

    if (cblk == 0) {
        ksacc += __shfl_xor_sync(0xffffffffu, ksacc, 1);
        if ((t & 1) == 0) {
            int dg = dblk * 128 + (t >> 1);
            atomicAdd(&g_acc[KV_SZ + (b * PH + (dg >> 5)) * DL + (dg & 31)], ksacc);
        }
    }
}

// ===================== compose: kv = Wv^T S + bv ksum^T =====================
// grid (32 bh, 8 c'-splits, 2 split-groups). z=0 sums sp 0..4, z=1 sums 5..8.
__global__ __launch_bounds__(256) void compose_kernel()
{
    __shared__ float ssum[32 * 68];   // [dl][cc] padded for float4
    __shared__ __half wv[64 * 64];    // [cv][cc]
    __shared__ float ks[32];

    const int bh = blockIdx.x, cs = blockIdx.y, z = blockIdx.z;
    const int b = bh >> 3, h = bh & 7;
    const int t = threadIdx.x;
    const int sp0 = z ? 5 : 0, sp1 = z ? S_NSPLIT : 5;

    {
        int dl = t >> 3, g = t & 7;
        float s[8];
#pragma unroll
        for (int k = 0; k < 8; k++) s[k] = 0.0f;
        for (int sp = sp0; sp < sp1; sp++) {
            uint4 p = *(const uint4*)&g_Sp[
                ((size_t)(sp * PB + b) * 256 + h * 32 + dl) * 512
                + cs * 64 + g * 8];
            float2 f0 = __half22float2(*(__half2*)&p.x);
            float2 f1 = __half22float2(*(__half2*)&p.y);
            float2 f2 = __half22float2(*(__half2*)&p.z);
            float2 f3 = __half22float2(*(__half2*)&p.w);
            s[0] += f0.x; s[1] += f0.y; s[2] += f1.x; s[3] += f1.y;
            s[4] += f2.x; s[5] += f2.y; s[6] += f3.x; s[7] += f3.y;
        }
        float4 lo = {s[0], s[1], s[2], s[3]};
        float4 hi = {s[4], s[5], s[6], s[7]};
        *(float4*)&ssum[dl * 68 + g * 8]     = lo;
        *(float4*)&ssum[dl * 68 + g * 8 + 4] = hi;
    }
#pragma unroll
    for (int i = 0; i < 2; i++) {
        int o = i * 256 + t;
        int cv = o >> 3, seg = o & 7;
        *(uint4*)&wv[cv * 64 + seg * 8] =
            *(const uint4*)&g_wth[(size_t)(256 + h * 64 + cv) * PC
                                  + cs * 64 + seg * 8];
    }
    if (cs == 0 && z == 0 && t < 32) ks[t] = g_acc[KV_SZ + bh * DL + t];
    __syncthreads();

    const int dl = t & 31, cvb = (t >> 5) * 8;
    float acc8[8];
#pragma unroll
    for (int i = 0; i < 8; i++) acc8[i] = 0.0f;

#pragma unroll
    for (int cc = 0; cc < 64; cc += 4) {
        float4 s4 = *(const float4*)&ssum[dl * 68 + cc];
#pragma unroll
        for (int i = 0; i < 8; i++) {
            uint2 w = *(const uint2*)&wv[(cvb + i) * 64 + cc];
            float2 w0 = __half22float2(*(__half2*)&w.x);
            float2 w1 = __half22float2(*(__half2*)&w.y);
            acc8[i] += w0.x * s4.x + w0.y * s4.y + w1.x * s4.z + w1.y * s4.w;
        }
    }
#pragma unroll
    for (int i = 0; i < 8; i++) {
        int cv = cvb + i;
        float a = acc8[i];
        if (cs == 0 && z == 0) a += g_bias[256 + h * 64 + cv] * ks[dl];
        atomicAdd(&g_acc[(size_t)bh * (DC * DL) + cv * DL + dl], a);
    }
}

// ===================== output via tensor cores =====================
// grid (32 bh, 8 row-tiles), 256 threads. Per CTA: 256 q rows of one (b,h).
#define QSW 24   // words per staged row (16 data + 8 pad; conflict-free LDS.64)

__global__ __launch_bounds__(256) void out_mma_kernel(float* __restrict__ out)
{
    __shared__ uint32_t qa[256 * QSW];   // 24576 B
    __shared__ uint32_t bt[72 * QSW];    //  6912 B

    const int t = threadIdx.x;
    const int bh = blockIdx.x;
    const int b = bh >> 3, h = bh & 7;
    const int grow0 = b * PM + blockIdx.y * 256;

#pragma unroll
    for (int i = 0; i < 4; i++) {
        int idx = i * 256 + t;
        int r = idx >> 2, s = idx & 3;
        asm volatile("cp.async.cg.shared.global [%0], [%1], 16;"
            :: "r"(smem_u32(qa + r * QSW + s * 4)),
               "l"(g_qp + (size_t)(grow0 + r) * PL + h * DL + s * 8));
    }
    asm volatile("cp.async.commit_group;" ::: "memory");

    const float* kvg = g_acc + (size_t)bh * DC * DL;
    __half* bth = (__half*)bt;
#pragma unroll
    for (int i = 0; i < 8; i++) {
        int idx = i * 256 + t;
        int n = idx >> 5, d = idx & 31;
        bth[n * (2 * QSW) + d] = __float2half_rn(kvg[idx]);
    }
    if (t < 32)
        bth[64 * (2 * QSW) + t] = __float2half_rn(g_acc[KV_SZ + bh * DL + t]);
    else if (t < 256) {
        int j = t - 32;
        if (j < 224) bth[(65 + (j >> 5)) * (2 * QSW) + (j & 31)] = __half(0.0f);
    }
    asm volatile("cp.async.wait_group 0;" ::: "memory");
    __syncthreads();

    const int wid = t >> 5, lane = t & 31, lr = lane >> 2, lc = lane & 3;
    const int wm = wid * 32;

    float acc[2][9][4];
#pragma unroll
    for (int mi = 0; mi < 2; mi++)
#pragma unroll
        for (int ni = 0; ni < 9; ni++)
#pragma unroll
            for (int j = 0; j < 4; j++) acc[mi][ni][j] = 0.0f;

#pragma unroll
    for (int j = 0; j < 2; j++) {
        const int ko = 8 * j + 2 * lc;
        uint32_t af[2][4], bf[9][2];
#pragma unroll
        for (int mi = 0; mi < 2; mi++) {
            const int r0 = wm + mi * 16 + lr;
            uint2 lo = *(const uint2*)&qa[r0 * QSW + ko];
            uint2 hi = *(const uint2*)&qa[(r0 + 8) * QSW + ko];
            af[mi][0] = lo.x; af[mi][1] = hi.x;
            af[mi][2] = lo.y; af[mi][3] = hi.y;
        }
#pragma unroll
        for (int ni = 0; ni < 9; ni++) {
            uint2 bb = *(const uint2*)&bt[(ni * 8 + lr) * QSW + ko];
            bf[ni][0] = bb.x; bf[ni][1] = bb.y;
        }
#pragma unroll
        for (int mi = 0; mi < 2; mi++)
#pragma unroll
            for (int ni = 0; ni < 9; ni++)
                asm volatile(
                    "mma.sync.aligned.m16n8k16.row.col.f32.f16.f16.f32 "
                    "{%0,%1,%2,%3}, {%4,%5,%6,%7}, {%8,%9}, {%0,%1,%2,%3};"
                    : "+f"(acc[mi][ni][0]), "+f"(acc[mi][ni][1]),
                      "+f"(acc[mi][ni][2]), "+f"(acc[mi][ni][3])
                    : "r"(af[mi][0]), "r"(af[mi][1]),
                      "r"(af[mi][2]), "r"(af[mi][3]),
                      "r"(bf[ni][0]), "r"(bf[ni][1]));
    }

#pragma unroll
    for (int mi = 0; mi < 2; mi++) {
        float dlo = __shfl_sync(0xffffffffu, acc[mi][8][0], lane & ~3);
        float dhi = __shfl_sync(0xffffffffu, acc[mi][8][2], lane & ~3);
        float zlo = 1.0f / (dlo + EPS);
        float zhi = 1.0f / (dhi + EPS);
        int rlo = grow0 + wm + mi * 16 + lr;
#pragma unroll
        for (int ni = 0; ni < 8; ni++) {
            int col = h * DC + ni * 8 + 2 * lc;
            float2 slo = {acc[mi][ni][0] * zlo, acc[mi][ni][1] * zlo};
            float2 shi = {acc[mi][ni][2] * zhi, acc[mi][ni][3] * zhi};
            *(float2*)&out[(size_t)rlo * PC + col]       = slo;
            *(float2*)&out[(size_t)(rlo + 8) * PC + col] = shi;
        }
    }
}

// ---------------------------------------------------------------------
extern "C" void kernel_launch(void* const* d_in, const int* in_sizes, int n_in,
                              void* d_out, int out_size)
{
    const float* input = (const float*)d_in[0];
    const float* query = (const float*)d_in[1];
    const float* Wq    = (const float*)d_in[2];
    const float* bq    = (const float*)d_in[3];
    const float* Wk    = (const float*)d_in[4];
    const float* bk    = (const float*)d_in[5];
    const float* Wv    = (const float*)d_in[6];
    const float* bv    = (const float*)d_in[7];
    float* out = (float*)d_out;
    (void)in_sizes; (void)n_in; (void)out_size;

    cudaFuncSetAttribute(kvq_gemm_kernel,
                         cudaFuncAttributeMaxDynamicSharedMemorySize, SMEM_GEMM);
    cudaFuncSetAttribute(s_gemm_kernel,
                         cudaFuncAttributeMaxDynamicSharedMemorySize, SMEM_S);

    // 1) prep: weight transposes (fp16) + bias gather + zero acc
    prep_kernel<<<dim3(32, 16), dim3(32, 8)>>>(Wk, Wv, Wq, bk, bv, bq);

    // 2) k|q projection GEMM with fused X^T fp16 write
    kvq_gemm_kernel<<<512 + 128, 256, SMEM_GEMM>>>(input, query);

    // 3) S^T = kt @ xt^T (9 uneven n-splits -> 288 CTAs) + ksum
    s_gemm_kernel<<<dim3(32, S_NSPLIT), 256, SMEM_S>>>();

    // 4) kv = Wv^T S + bv ksum^T (split-groups for 2x grid)
    compose_kernel<<<dim3(32, 8, 2), 256>>>();

    // 5) output on tensor cores (z via ksum column)
    out_mma_kernel<<<dim3(32, 8), 256>>>(out);
}

// round 17
// speedup vs baseline: 1.0378x; 1.0378x over previous
#include <cuda_runtime.h>
#include <cuda_fp16.h>
#include <cstdint>
#include <math.h>

// Problem constants (LinearAttention_22943715295778)
#define PB 4
#define PN 8192
#define PM 2048
#define PC 512
#define PL 256
#define PH 8
#define DL 32   // L/H
#define DC 64   // C/H
#define EPS 1e-6f

#define KV_SZ (PB*PH*DC*DL)                       // 65536
#define NACC (KV_SZ + PB*PH*DL)                   // 66560
#define S_NSPLIT 9

// -------- device-global scratch (allocation-free requirement) --------
__device__ __half g_kt[PB * PH * DL * PN];        // 16 MB : k^T [b*256+dg][n], fp16, post-elu
__device__ __half g_xt[PB * PC * PN];             // 32 MB : X^T [b*512+c'][n], fp16
__device__ __half g_qp[PB * PM * PL];             //  4 MB : q [row][256], fp16, post-elu
__device__ __half g_Sp[S_NSPLIT * PB * 256 * 512];//  9 MB : fp16 split partials of S^T
__device__ float  g_acc[NACC];                    // kv (65536) + ksum (1024)
__device__ __half g_wth[1024 * PC];               // rows: [WkT 256][WvT 512][WqT 256], fp16
__device__ float  g_bias[1024];                   // [bk | bv | bq]

// ===================== helpers =====================
__device__ __forceinline__ uint32_t smem_u32(const void* p) {
    uint32_t a;
    asm("{ .reg .u64 t; cvta.to.shared.u64 t, %1; cvt.u32.u64 %0, t; }"
        : "=r"(a) : "l"(p));
    return a;
}
// pack two fp32 -> one fp16x2 register (F2FP.PACK); lo in low half
__device__ __forceinline__ uint32_t pack_h2(float lo, float hi) {
    uint32_t r;
    asm("cvt.rn.f16x2.f32 %0, %1, %2;" : "=r"(r) : "f"(hi), "f"(lo));
    return r;
}

// ===================== prep: weight transposes + bias + zero =====================
__global__ __launch_bounds__(256) void prep_kernel(
    const float* __restrict__ Wk, const float* __restrict__ Wv,
    const float* __restrict__ Wq,
    const float* __restrict__ bk, const float* __restrict__ bv,
    const float* __restrict__ bq)
{
    __shared__ float tile[32][33];
    const int n0 = blockIdx.x * 32, k0 = blockIdx.y * 32;
    const float *W, *bsrc; int N, ns;
    if (n0 < 256)      { W = Wk; bsrc = bk; N = PL; ns = n0; }
    else if (n0 < 768) { W = Wv; bsrc = bv; N = PC; ns = n0 - 256; }
    else               { W = Wq; bsrc = bq; N = PL; ns = n0 - 768; }
    const int tx = threadIdx.x, ty = threadIdx.y;
    for (int i = ty; i < 32; i += 8)
        tile[i][tx] = W[(size_t)(k0 + i) * N + ns + tx];
    __syncthreads();
    for (int i = ty; i < 32; i += 8)
        g_wth[(size_t)(n0 + i) * PC + k0 + tx] = __float2half_rn(tile[tx][i]);
    if (blockIdx.y == 0 && ty == 0)
        g_bias[n0 + tx] = bsrc[ns + tx];
    if (blockIdx.y == 1) {
        int t = ty * 32 + tx;
#pragma unroll
        for (int i = 0; i < 9; i++) {
            int j = blockIdx.x * 256 + t + i * 8192;
            if (j < NACC) g_acc[j] = 0.0f;
        }
    }
}

// ===================== fp16 mma mainloop, fp32 A operand =====================
#define TMm 128
#define TNn 128
#define BKh 64
#define ASW 64                        // fp32 words per A row (XOR swizzled)
#define BSW 40                        // uint32 words per fp16 row (64 fp16 + pad)
#define ATILEW (128 * ASW)
#define BTILEW (128 * BSW)
#define NCHh (PC / BKh)               // 8
#define SMEM_GEMM ((2 * ATILEW + 2 * BTILEW) * 4)   // 106496 bytes

__device__ __forceinline__ void mma_tile_loop_f32a(
    const float* __restrict__ Ag0,
    const __half* __restrict__ Bg0,
    uint32_t* sm, int t, float acc[2][8][4],
    int cx0, __half* __restrict__ xt_dst, int xt_n0)
{
    uint32_t* As = sm;
    uint32_t* Bs = sm + 2 * ATILEW;
    const int wid = t >> 5, lane = t & 31;
    const int lr = lane >> 2, lc = lane & 3;
    const int wm = (wid & 3) * 32, wn = (wid >> 2) * 64;

    auto stage = [&](int c, int buf) {
        const float*  Ag = Ag0 + c * BKh;
        const __half* Bg = Bg0 + c * BKh;
        uint32_t* Ad = As + buf * ATILEW;
        uint32_t* Bd = Bs + buf * BTILEW;
#pragma unroll
        for (int i = 0; i < 8; i++) {
            int idx = i * 256 + t;
            int r = idx >> 4, s = idx & 15;
            int ss = s ^ ((r & 1) << 2);
            asm volatile("cp.async.cg.shared.global [%0], [%1], 16;"
                :: "r"(smem_u32(Ad + r * ASW + ss * 4)),
                   "l"(Ag + (size_t)r * PC + s * 4));
        }
#pragma unroll
        for (int i = 0; i < 4; i++) {
            int idx = i * 256 + t;
            int r = idx >> 3, s = idx & 7;
            asm volatile("cp.async.cg.shared.global [%0], [%1], 16;"
                :: "r"(smem_u32(Bd + r * BSW + s * 4)),
                   "l"(Bg + (size_t)r * PC + s * 8));
        }
        asm volatile("cp.async.commit_group;" ::: "memory");
    };

    auto compute = [&](int buf) {
        const uint32_t* Ab = As + buf * ATILEW;
        const uint32_t* Bb = Bs + buf * BTILEW;
#pragma unroll
        for (int j = 0; j < 4; j++) {
            uint32_t af[2][4], bf[8][2];
            const int aoff = 16 * (j ^ (lr & 1)) + 4 * lc;
#pragma unroll
            for (int mi = 0; mi < 2; mi++) {
                const int r0 = wm + mi * 16 + lr;
                float4 f0 = *(const float4*)(Ab + r0 * ASW + aoff);
                float4 f1 = *(const float4*)(Ab + (r0 + 8) * ASW + aoff);
                af[mi][0] = pack_h2(f0.x, f0.y);
                af[mi][2] = pack_h2(f0.z, f0.w);
                af[mi][1] = pack_h2(f1.x, f1.y);
                af[mi][3] = pack_h2(f1.z, f1.w);
            }
            const int ko = 8 * j + 2 * lc;
#pragma unroll
            for (int ni = 0; ni < 8; ni++) {
                uint2 b = *(const uint2*)&Bb[(wn + ni * 8 + lr) * BSW + ko];
                bf[ni][0] = b.x; bf[ni][1] = b.y;
            }
#pragma unroll
            for (int mi = 0; mi < 2; mi++)
#pragma unroll
                for (int ni = 0; ni < 8; ni++)
                    asm volatile(
                        "mma.sync.aligned.m16n8k16.row.col.f32.f16.f16.f32 "
                        "{%0,%1,%2,%3}, {%4,%5,%6,%7}, {%8,%9}, {%0,%1,%2,%3};"
                        : "+f"(acc[mi][ni][0]), "+f"(acc[mi][ni][1]),
                          "+f"(acc[mi][ni][2]), "+f"(acc[mi][ni][3])
                        : "r"(af[mi][0]), "r"(af[mi][1]),
                          "r"(af[mi][2]), "r"(af[mi][3]),
                          "r"(bf[ni][0]), "r"(bf[ni][1]));
        }
    };

    // Fused X^T write (reads staged fp32 A tile).
    auto xt_write = [&](int c, int buf) {
        const uint32_t* Ab = As + buf * ATILEW;
        const int cw = (wid & 1) * 32 + lane;
        const int rb = (wid >> 1) * 32;
        __half* dst = xt_dst + (size_t)(c * BKh + cw) * PN + xt_n0 + rb;
        const int cbase = ((cw >> 2) << 2) + (cw & 3);
#pragma unroll
        for (int g = 0; g < 4; g++) {
            uint32_t h2[4];
#pragma unroll
            for (int p = 0; p < 4; p++) {
                int r0 = rb + g * 8 + 2 * p;
                float f0 = __uint_as_float(
                    Ab[r0 * ASW + (cbase ^ (((r0 & 1) << 4)))]);
                float f1 = __uint_as_float(
                    Ab[(r0 + 1) * ASW + (cbase ^ ((((r0 + 1) & 1) << 4)))]);
                h2[p] = pack_h2(f0, f1);
            }
            uint4 val = {h2[0], h2[1], h2[2], h2[3]};
            *(uint4*)(dst + g * 8) = val;
        }
    };

    stage(0, 0);
    for (int c = 0; c < NCHh; c++) {
        if (c + 1 < NCHh) {
            stage(c + 1, (c + 1) & 1);
            asm volatile("cp.async.wait_group 1;" ::: "memory");
        } else {
            asm volatile("cp.async.wait_group 0;" ::: "memory");
        }
        __syncthreads();
        compute(c & 1);
        if (xt_dst && c >= cx0 && c < cx0 + 4)
            xt_write(c, c & 1);
        __syncthreads();
    }
}

// ===================== k|q projection (+fused X^T) kernel =====================
#define TSTR 136   // fp16 stride of k-transpose buffer rows

__global__ __launch_bounds__(256, 2) void kvq_gemm_kernel(
    const float* __restrict__ X, const float* __restrict__ Q)
{
    extern __shared__ uint32_t smw[];
    const int id = blockIdx.x;
    const int t = threadIdx.x;

    float acc[2][8][4];
#pragma unroll
    for (int mi = 0; mi < 2; mi++)
#pragma unroll
        for (int ni = 0; ni < 8; ni++)
#pragma unroll
            for (int j = 0; j < 4; j++) acc[mi][ni][j] = 0.0f;

    if (id < 512) {
        // ---- k projection GEMM + fused X^T write ----
        const int panel = id >> 1, sub = id & 1;
        const int row0 = panel * TMm;
        const int col0 = sub * TNn;   // 0 or 128
        const int b = row0 >> 13, n0 = row0 & 8191;

        mma_tile_loop_f32a(X + (size_t)row0 * PC, g_wth + (size_t)col0 * PC,
                           smw, t, acc,
                           sub * 4, g_xt + (size_t)b * PC * PN, n0);

        const int wid = t >> 5, lane = t & 31, lr = lane >> 2, lc = lane & 3;
        const int wm = (wid & 3) * 32, wn = (wid >> 2) * 64;

        __half* st = (__half*)smw;   // [128 cols][TSTR]
#pragma unroll
        for (int mi = 0; mi < 2; mi++)
#pragma unroll
            for (int ni = 0; ni < 8; ni++) {
                int r  = wm + mi * 16 + lr;
                int cc = wn + ni * 8 + 2 * lc;
                float b0 = g_bias[col0 + cc], b1 = g_bias[col0 + cc + 1];
                float x0 = acc[mi][ni][0] + b0;
                float x1 = acc[mi][ni][1] + b1;
                float x2 = acc[mi][ni][2] + b0;
                float x3 = acc[mi][ni][3] + b1;
                x0 = x0 > 0.0f ? x0 + 1.0f : expf(x0);
                x1 = x1 > 0.0f ? x1 + 1.0f : expf(x1);
                x2 = x2 > 0.0f ? x2 + 1.0f : expf(x2);
                x3 = x3 > 0.0f ? x3 + 1.0f : expf(x3);
                st[cc * TSTR + r]           = __float2half_rn(x0);
                st[(cc + 1) * TSTR + r]     = __float2half_rn(x1);
                st[cc * TSTR + r + 8]       = __float2half_rn(x2);
                st[(cc + 1) * TSTR + r + 8] = __float2half_rn(x3);
            }
        __syncthreads();

#pragma unroll
        for (int i = 0; i < 8; i++) {
            int flat = t + i * 256;
            int col = flat >> 4, seg = flat & 15;
            uint4 val = *(const uint4*)&st[col * TSTR + seg * 8];
            int dg = col0 + col;
            *(uint4*)&g_kt[(size_t)(b * 256 + dg) * PN + n0 + seg * 8] = val;
        }
        return;
    }

    // ---- q projection GEMM ----
    const int j = id - 512;
    const int col0 = 768 + (j & 1) * TNn;
    const int row0 = (j >> 1) * TMm;

    mma_tile_loop_f32a(Q + (size_t)row0 * PC, g_wth + (size_t)col0 * PC,
                       smw, t, acc, 0, nullptr, 0);

    const int wid = t >> 5, lane = t & 31, lr = lane >> 2, lc = lane & 3;
    const int wm = (wid & 3) * 32, wn = (wid >> 2) * 64;
#pragma unroll
    for (int mi = 0; mi < 2; mi++)
#pragma unroll
        for (int ni = 0; ni < 8; ni++) {
            int r  = row0 + wm + mi * 16 + lr;
            int cb = wn + ni * 8 + 2 * lc;
            int cc = (col0 - 768) + cb;
            float b0 = g_bias[col0 + cb];
            float b1 = g_bias[col0 + cb + 1];
            float x0 = acc[mi][ni][0] + b0;
            float x1 = acc[mi][ni][1] + b1;
            float x2 = acc[mi][ni][2] + b0;
            float x3 = acc[mi][ni][3] + b1;
            x0 = x0 > 0.0f ? x0 + 1.0f : expf(x0);
            x1 = x1 > 0.0f ? x1 + 1.0f : expf(x1);
            x2 = x2 > 0.0f ? x2 + 1.0f : expf(x2);
            x3 = x3 > 0.0f ? x3 + 1.0f : expf(x3);
            *(uint32_t*)&g_qp[(size_t)r * PL + cc]       = pack_h2(x0, x1);
            *(uint32_t*)&g_qp[(size_t)(r + 8) * PL + cc] = pack_h2(x2, x3);
        }
}

// ===================== S kernel: S^T[d][c'] = sum_n kt[d][n] * xt[c'][n] =====================
// grid (32, 9): uneven n-splits (chunks [y*128/9, (y+1)*128/9)) -> 288 CTAs.
#define SMEM_S (4 * BTILEW * 4)         // 81920 bytes

__global__ __launch_bounds__(256, 2) void s_gemm_kernel()
{
    extern __shared__ uint32_t smw[];
    uint32_t* As = smw;                 // kt tiles [2][128][BSW]
    uint32_t* Bs = smw + 2 * BTILEW;    // xt tiles [2][128][BSW]

    const int bx = blockIdx.x;
    const int cblk = bx & 3;
    const int dblk = (bx >> 2) & 1;
    const int b    = bx >> 3;
    const int y    = blockIdx.y;
    const int cst  = (y * 128) / S_NSPLIT;
    const int nch  = ((y + 1) * 128) / S_NSPLIT - cst;
    const int n0   = cst * BKh;
    const int t = threadIdx.x;
    const int wid = t >> 5, lane = t & 31, lr = lane >> 2, lc = lane & 3;
    const int wm = (wid & 3) * 32, wn = (wid >> 2) * 64;

    const __half* Ag0 = g_kt + (size_t)(b * 256 + dblk * 128) * PN + n0;
    const __half* Bg0 = g_xt + (size_t)(b * PC  + cblk * 128) * PN + n0;

    auto stage = [&](int c, int buf) {
        const __half* Ag = Ag0 + c * BKh;
        const __half* Bg = Bg0 + c * BKh;
        uint32_t* Ad = As + buf * BTILEW;
        uint32_t* Bd = Bs + buf * BTILEW;
#pragma unroll
        for (int i = 0; i < 4; i++) {
            int idx = i * 256 + t;
            int r = idx >> 3, seg = idx & 7;
            asm volatile("cp.async.cg.shared.global [%0], [%1], 16;"
                :: "r"(smem_u32(Ad + r * BSW + seg * 4)),
                   "l"(Ag + (size_t)r * PN + seg * 8));
            asm volatile("cp.async.cg.shared.global [%0], [%1], 16;"
                :: "r"(smem_u32(Bd + r * BSW + seg * 4)),
                   "l"(Bg + (size_t)r * PN + seg * 8));
        }
        asm volatile("cp.async.commit_group;" ::: "memory");
    };

    float acc[2][8][4];
#pragma unroll
    for (int mi = 0; mi < 2; mi++)
#pragma unroll
        for (int ni = 0; ni < 8; ni++)
#pragma unroll
            for (int j = 0; j < 4; j++) acc[mi][ni][j] = 0.0f;
    float ksacc = 0.0f;

    auto compute = [&](int buf) {
        const uint32_t* Ab = As + buf * BTILEW;
        const uint32_t* Bb = Bs + buf * BTILEW;
#pragma unroll
        for (int j = 0; j < 4; j++) {
            const int ko = 8 * j + 2 * lc;
            uint32_t af[2][4], bf[8][2];
#pragma unroll
            for (int mi = 0; mi < 2; mi++) {
                uint2 lo = *(const uint2*)&Ab[(wm + mi * 16 + lr) * BSW + ko];
                uint2 hi = *(const uint2*)&Ab[(wm + mi * 16 + lr + 8) * BSW + ko];
                af[mi][0] = lo.x; af[mi][1] = hi.x;
                af[mi][2] = lo.y; af[mi][3] = hi.y;
            }
#pragma unroll
            for (int ni = 0; ni < 8; ni++) {
                uint2 bb = *(const uint2*)&Bb[(wn + ni * 8 + lr) * BSW + ko];
                bf[ni][0] = bb.x; bf[ni][1] = bb.y;
            }
#pragma unroll
            for (int mi = 0; mi < 2; mi++)
#pragma unroll
                for (int ni = 0; ni < 8; ni++)
                    asm volatile(
                        "mma.sync.aligned.m16n8k16.row.col.f32.f16.f16.f32 "
                        "{%0,%1,%2,%3}, {%4,%5,%6,%7}, {%8,%9}, {%0,%1,%2,%3};"
                        : "+f"(acc[mi][ni][0]), "+f"(acc[mi][ni][1]),
                          "+f"(acc[mi][ni][2]), "+f"(acc[mi][ni][3])
                        : "r"(af[mi][0]), "r"(af[mi][1]),
                          "r"(af[mi][2]), "r"(af[mi][3]),
                          "r"(bf[ni][0]), "r"(bf[ni][1]));
        }
        if (cblk == 0) {   // ksum partial: thread t sums half of row t>>1
            const uint32_t* kp = Ab + (t >> 1) * BSW + (t & 1) * 16;
#pragma unroll
            for (int i = 0; i < 16; i++) {
                float2 f = __half22float2(*(const __half2*)&kp[i]);
                ksacc += f.x + f.y;
            }
        }
    };

    stage(0, 0);
    for (int c = 0; c < nch; c++) {
        if (c + 1 < nch) {
            stage(c + 1, (c + 1) & 1);
            asm volatile("cp.async.wait_group 1;" ::: "memory");
        } else {
            asm volatile("cp.async.wait_group 0;" ::: "memory");
        }
        __syncthreads();
        compute(c & 1);
        __syncthreads();
    }

    // non-atomic fp16 partial store
    __half* dst = g_Sp + ((size_t)(y * PB + b) * 256 + dblk * 128) * 512
                  + cblk * 128;
#pragma unroll
    for (int mi = 0; mi < 2; mi++)
#pragma unroll
        for (int ni = 0; ni < 8; ni++) {
            int row = wm + mi * 16 + lr;
            int col = wn + ni * 8 + 2 * lc;
            *(uint32_t*)&dst[(size_t)row * 512 + col] =
                pack_h2(acc[mi][ni][0], acc[mi][ni][1]);
            *(uint32_t*)&dst[(size_t)(row + 8) * 512 + col] =
                pack_h2(acc[mi][ni][2], acc[mi][ni][3]);
        }

    if (cblk == 0) {
        ksacc += __shfl_xor_sync(0xffffffffu, ksacc, 1);
        if ((t & 1) == 0) {
            int dg = dblk * 128 + (t >> 1);
            atomicAdd(&g_acc[KV_SZ + (b * PH + (dg >> 5)) * DL + (dg & 31)], ksacc);
        }
    }
}

// ===================== compose: kv = Wv^T S + bv ksum^T =====================
// grid (32 bh, 8 c'-splits), 256 threads. Single pass over all 9 splits.
__global__ __launch_bounds__(256) void compose_kernel()
{
    __shared__ float ssum[32 * 68];   // [dl][cc] padded for float4
    __shared__ __half wv[64 * 64];    // [cv][cc]
    __shared__ float ks[32];

    const int bh = blockIdx.x, cs = blockIdx.y;
    const int b = bh >> 3, h = bh & 7;
    const int t = threadIdx.x;

    {
        int dl = t >> 3, g = t & 7;
        float s[8];
#pragma unroll
        for (int k = 0; k < 8; k++) s[k] = 0.0f;
#pragma unroll
        for (int sp = 0; sp < S_NSPLIT; sp++) {
            uint4 p = *(const uint4*)&g_Sp[
                ((size_t)(sp * PB + b) * 256 + h * 32 + dl) * 512
                + cs * 64 + g * 8];
            float2 f0 = __half22float2(*(__half2*)&p.x);
            float2 f1 = __half22float2(*(__half2*)&p.y);
            float2 f2 = __half22float2(*(__half2*)&p.z);
            float2 f3 = __half22float2(*(__half2*)&p.w);
            s[0] += f0.x; s[1] += f0.y; s[2] += f1.x; s[3] += f1.y;
            s[4] += f2.x; s[5] += f2.y; s[6] += f3.x; s[7] += f3.y;
        }
        float4 lo = {s[0], s[1], s[2], s[3]};
        float4 hi = {s[4], s[5], s[6], s[7]};
        *(float4*)&ssum[dl * 68 + g * 8]     = lo;
        *(float4*)&ssum[dl * 68 + g * 8 + 4] = hi;
    }
#pragma unroll
    for (int i = 0; i < 2; i++) {
        int o = i * 256 + t;
        int cv = o >> 3, seg = o & 7;
        *(uint4*)&wv[cv * 64 + seg * 8] =
            *(const uint4*)&g_wth[(size_t)(256 + h * 64 + cv) * PC
                                  + cs * 64 + seg * 8];
    }
    if (cs == 0 && t < 32) ks[t] = g_acc[KV_SZ + bh * DL + t];
    __syncthreads();

    const int dl = t & 31, cvb = (t >> 5) * 8;
    float acc8[8];
#pragma unroll
    for (int i = 0; i < 8; i++) acc8[i] = 0.0f;

#pragma unroll
    for (int cc = 0; cc < 64; cc += 4) {
        float4 s4 = *(const float4*)&ssum[dl * 68 + cc];
#pragma unroll
        for (int i = 0; i < 8; i++) {
            uint2 w = *(const uint2*)&wv[(cvb + i) * 64 + cc];
            float2 w0 = __half22float2(*(__half2*)&w.x);
            float2 w1 = __half22float2(*(__half2*)&w.y);
            acc8[i] += w0.x * s4.x + w0.y * s4.y + w1.x * s4.z + w1.y * s4.w;
        }
    }
#pragma unroll
    for (int i = 0; i < 8; i++) {
        int cv = cvb + i;
        float a = acc8[i];
        if (cs == 0) a += g_bias[256 + h * 64 + cv] * ks[dl];
        atomicAdd(&g_acc[(size_t)bh * (DC * DL) + cv * DL + dl], a);
    }
}

// ===================== output via tensor cores =====================
// grid (32 bh, 8 row-tiles), 256 threads. Per CTA: 256 q rows of one (b,h).
#define QSW 24   // words per staged row (16 data + 8 pad; conflict-free LDS.64)

__global__ __launch_bounds__(256) void out_mma_kernel(float* __restrict__ out)
{
    __shared__ uint32_t qa[256 * QSW];   // 24576 B
    __shared__ uint32_t bt[72 * QSW];    //  6912 B

    const int t = threadIdx.x;
    const int bh = blockIdx.x;
    const int b = bh >> 3, h = bh & 7;
    const int grow0 = b * PM + blockIdx.y * 256;

#pragma unroll
    for (int i = 0; i < 4; i++) {
        int idx = i * 256 + t;
        int r = idx >> 2, s = idx & 3;
        asm volatile("cp.async.cg.shared.global [%0], [%1], 16;"
            :: "r"(smem_u32(qa + r * QSW + s * 4)),
               "l"(g_qp + (size_t)(grow0 + r) * PL + h * DL + s * 8));
    }
    asm volatile("cp.async.commit_group;" ::: "memory");

    const float* kvg = g_acc + (size_t)bh * DC * DL;
    __half* bth = (__half*)bt;
#pragma unroll
    for (int i = 0; i < 8; i++) {
        int idx = i * 256 + t;
        int n = idx >> 5, d = idx & 31;
        bth[n * (2 * QSW) + d] = __float2half_rn(kvg[idx]);
    }
    if (t < 32)
        bth[64 * (2 * QSW) + t] = __float2half_rn(g_acc[KV_SZ + bh * DL + t]);
    else if (t < 256) {
        int j = t - 32;
        if (j < 224) bth[(65 + (j >> 5)) * (2 * QSW) + (j & 31)] = __half(0.0f);
    }
    asm volatile("cp.async.wait_group 0;" ::: "memory");
    __syncthreads();

    const int wid = t >> 5, lane = t & 31, lr = lane >> 2, lc = lane & 3;
    const int wm = wid * 32;

    float acc[2][9][4];
#pragma unroll
    for (int mi = 0; mi < 2; mi++)
#pragma unroll
        for (int ni = 0; ni < 9; ni++)
#pragma unroll
            for (int j = 0; j < 4; j++) acc[mi][ni][j] = 0.0f;

#pragma unroll
    for (int j = 0; j < 2; j++) {
        const int ko = 8 * j + 2 * lc;
        uint32_t af[2][4], bf[9][2];
#pragma unroll
        for (int mi = 0; mi < 2; mi++) {
            const int r0 = wm + mi * 16 + lr;
            uint2 lo = *(const uint2*)&qa[r0 * QSW + ko];
            uint2 hi = *(const uint2*)&qa[(r0 + 8) * QSW + ko];
            af[mi][0] = lo.x; af[mi][1] = hi.x;
            af[mi][2] = lo.y; af[mi][3] = hi.y;
        }
#pragma unroll
        for (int ni = 0; ni < 9; ni++) {
            uint2 bb = *(const uint2*)&bt[(ni * 8 + lr) * QSW + ko];
            bf[ni][0] = bb.x; bf[ni][1] = bb.y;
        }
#pragma unroll
        for (int mi = 0; mi < 2; mi++)
#pragma unroll
            for (int ni = 0; ni < 9; ni++)
                asm volatile(
                    "mma.sync.aligned.m16n8k16.row.col.f32.f16.f16.f32 "
                    "{%0,%1,%2,%3}, {%4,%5,%6,%7}, {%8,%9}, {%0,%1,%2,%3};"
                    : "+f"(acc[mi][ni][0]), "+f"(acc[mi][ni][1]),
                      "+f"(acc[mi][ni][2]), "+f"(acc[mi][ni][3])
                    : "r"(af[mi][0]), "r"(af[mi][1]),
                      "r"(af[mi][2]), "r"(af[mi][3]),
                      "r"(bf[ni][0]), "r"(bf[ni][1]));
    }

#pragma unroll
    for (int mi = 0; mi < 2; mi++) {
        float dlo = __shfl_sync(0xffffffffu, acc[mi][8][0], lane & ~3);
        float dhi = __shfl_sync(0xffffffffu, acc[mi][8][2], lane & ~3);
        float zlo = 1.0f / (dlo + EPS);
        float zhi = 1.0f / (dhi + EPS);
        int rlo = grow0 + wm + mi * 16 + lr;
#pragma unroll
        for (int ni = 0; ni < 8; ni++) {
            int col = h * DC + ni * 8 + 2 * lc;
            float2 slo = {acc[mi][ni][0] * zlo, acc[mi][ni][1] * zlo};
            float2 shi = {acc[mi][ni][2] * zhi, acc[mi][ni][3] * zhi};
            *(float2*)&out[(size_t)rlo * PC + col]       = slo;
            *(float2*)&out[(size_t)(rlo + 8) * PC + col] = shi;
        }
    }
}

// ---------------------------------------------------------------------
extern "C" void kernel_launch(void* const* d_in, const int* in_sizes, int n_in,
                              void* d_out, int out_size)
{
    const float* input = (const float*)d_in[0];
    const float* query = (const float*)d_in[1];
    const float* Wq    = (const float*)d_in[2];
    const float* bq    = (const float*)d_in[3];
    const float* Wk    = (const float*)d_in[4];
    const float* bk    = (const float*)d_in[5];
    const float* Wv    = (const float*)d_in[6];
    const float* bv    = (const float*)d_in[7];
    float* out = (float*)d_out;
    (void)in_sizes; (void)n_in; (void)out_size;

    cudaFuncSetAttribute(kvq_gemm_kernel,
                         cudaFuncAttributeMaxDynamicSharedMemorySize, SMEM_GEMM);
    cudaFuncSetAttribute(s_gemm_kernel,
                         cudaFuncAttributeMaxDynamicSharedMemorySize, SMEM_S);

    // 1) prep: weight transposes (fp16) + bias gather + zero acc
    prep_kernel<<<dim3(32, 16), dim3(32, 8)>>>(Wk, Wv, Wq, bk, bv, bq);

    // 2) k|q projection GEMM with fused X^T fp16 write
    kvq_gemm_kernel<<<512 + 128, 256, SMEM_GEMM>>>(input, query);

    // 3) S^T = kt @ xt^T (9 uneven n-splits -> 288 CTAs) + ksum
    s_gemm_kernel<<<dim3(32, S_NSPLIT), 256, SMEM_S>>>();

    // 4) kv = Wv^T S + bv ksum^T (single pass, grid (32,8))
    compose_kernel<<<dim3(32, 8), 256>>>();

    // 5) output on tensor cores (z via ksum column)
    out_mma_kernel<<<dim3(32, 8), 256>>>(out);
}